// round 13
// baseline (speedup 1.0000x reference)
#include <cuda_runtime.h>

#define BATCH 8
#define CH    64
#define HH    256
#define WW    256
#define TW    16
#define NT    16                 // tiles along W
#define NCTA  (BATCH * NT)       // 128 CTAs, one wave
#define NBULK 512                // 64 co x 8 ci-groups
#define NTHR  576                // + 2 edge warps
#define CIPT  8                  // ci per thread
#define NCIG  8
#define PSTR  18                 // pp row stride in u64 (144 B, 16B-aligned)

typedef unsigned long long u64;

union F4U { float4 f; u64 u[2]; };

__device__ int   g_progress[NCTA];
__device__ float g_halo[2][NCTA][2][CH];   // [row parity][cta][left/right edge][ch]

struct SMEMT {
    u64   pp[2][CH][PSTR];       // pair rows (v[j-1],v[j]), dbl buf     18 KB
    u64   red[NCIG][NCIG][CH];   // partials [cig][pair][co]             32 KB
    float wE0[CH][CH];           // tap-0 weights, [ci][co]              16 KB
    float wE2[CH][CH];           // tap-2 weights, [ci][co]              16 KB
    float hL[CH], hR[CH];        // neighbor halo columns (row h-1)
    float corrL[CH], corrR[CH];  // halo corrections per co
};

// ---- packed f32x2 ops ------------------------------------------------------
static __device__ __forceinline__ u64 fma2(u64 a, u64 b, u64 c) {
    u64 d; asm("fma.rn.f32x2 %0, %1, %2, %3;" : "=l"(d) : "l"(a), "l"(b), "l"(c)); return d;
}
static __device__ __forceinline__ u64 add2(u64 a, u64 b) {
    u64 d; asm("add.rn.f32x2 %0, %1, %2;" : "=l"(d) : "l"(a), "l"(b)); return d;
}
static __device__ __forceinline__ u64 splat2(float x) {
    u64 r; asm("mov.b64 %0, {%1, %1};" : "=l"(r) : "f"(x)); return r;
}
static __device__ __forceinline__ void unpack2(u64 v, float& lo, float& hi) {
    unsigned a, b;
    asm("mov.b64 {%0,%1}, %2;" : "=r"(a), "=r"(b) : "l"(v));
    lo = __uint_as_float(a); hi = __uint_as_float(b);
}
static __device__ __forceinline__ float ftanh(float x) {
    float e = __expf(2.0f * x);
    return 1.0f - __fdividef(2.0f, e + 1.0f);
}

// ---- release/acquire flag ops ----------------------------------------------
static __device__ __forceinline__ int ld_acq(const int* p) {
    int v;
    asm volatile("ld.acquire.gpu.global.b32 %0, [%1];" : "=r"(v) : "l"(p));
    return v;
}
static __device__ __forceinline__ void st_rel(int* p, int v) {
    asm volatile("st.release.gpu.global.b32 [%0], %1;" :: "l"(p), "r"(v) : "memory");
}

__global__ void reset_kernel() {
    if (threadIdx.x < NCTA) g_progress[threadIdx.x] = -1;
}

__global__ void __launch_bounds__(NTHR, 1)
spatial_kernel(const float* __restrict__ X, const float* __restrict__ Wc,
               const float* __restrict__ bc, float* __restrict__ out) {
    extern __shared__ char smraw[];
    SMEMT* sm = reinterpret_cast<SMEMT*>(smraw);

    const int tid = threadIdx.x;
    const int bid = blockIdx.x;
    const int b   = bid >> 4;
    const int t   = bid & 15;            // tile position along W
    const int w0  = t * TW;

    // bulk-thread identity (valid only for tid < NBULK)
    const int co  = tid & 63;
    const int cig = (tid & 511) >> 6;
    const int o0  = cig * 2;

    // ---- one-time init ----
    // edge-weight tables wE0/wE2 in [ci][co] layout
    for (int idx = tid; idx < CH * CH; idx += NTHR) {
        int ci = idx >> 6, c = idx & 63;
        sm->wE0[ci][c] = Wc[((size_t)c * CH + ci) * 3 + 0];
        sm->wE2[ci][c] = Wc[((size_t)c * CH + ci) * 3 + 2];
    }
    if (tid < CH) {
        sm->corrL[tid] = 0.f; sm->corrR[tid] = 0.f;
        sm->hL[tid] = 0.f;    sm->hR[tid] = 0.f;
        reinterpret_cast<float2*>(&sm->pp[0][tid][0])->x  = 0.f;
        reinterpret_cast<float2*>(&sm->pp[1][tid][0])->x  = 0.f;
        reinterpret_cast<float2*>(&sm->pp[0][tid][16])->y = 0.f;
        reinterpret_cast<float2*>(&sm->pp[1][tid][16])->y = 0.f;
    }

    // bulk: weights (8 ci x 3 taps) into registers
    float wr[CIPT * 3];
    float bias = 0.f;
    if (tid < NBULK) {
        const float4* wp = reinterpret_cast<const float4*>(
            Wc + ((size_t)co * CH + cig * CIPT) * 3);
#pragma unroll
        for (int i = 0; i < 6; i++) {
            float4 v = wp[i];
            wr[i * 4 + 0] = v.x; wr[i * 4 + 1] = v.y;
            wr[i * 4 + 2] = v.z; wr[i * 4 + 3] = v.w;
        }
        bias = bc[co];
    }

    // ---- row 0: Y[0] = X[0] ----
    const size_t chb = ((size_t)(b * CH + co) * HH) * WW + w0;
    if (tid < NBULK) {
        float2 x2 = *reinterpret_cast<const float2*>(X + chb + o0);
        *reinterpret_cast<float2*>(out + chb + o0) = x2;
        float2* pr = reinterpret_cast<float2*>(&sm->pp[0][co][0]);
        pr[o0].y = x2.x; pr[o0 + 1].x = x2.x;
        pr[o0 + 1].y = x2.y; pr[o0 + 2].x = x2.y;
        if (cig == 0)        g_halo[0][bid][0][co] = x2.x;   // w = 0
        if (cig == NCIG - 1) g_halo[0][bid][1][co] = x2.y;   // w = 15
    }
    __syncthreads();
    if (tid == NBULK) st_rel(&g_progress[bid], 0);

    int cur = 0;
    for (int h = 1; h < HH; h++) {
        const int par  = (h - 1) & 1;
        const int need = h - 1;
        const size_t rb = chb + (size_t)h * WW;
        float2 x2;

        if (tid < NBULK) {
            // ================= BULK: conv partials (no neighbor dep) ========
            x2 = *reinterpret_cast<const float2*>(X + rb + o0);
            u64 s[8];
#pragma unroll
            for (int p = 0; p < 8; p++) s[p] = 0ull;
            const u64* rowbase = &sm->pp[cur][cig * CIPT][0];
#pragma unroll
            for (int j = 0; j < CIPT; j++) {
                const u64* q = rowbase + j * PSTR;
                const float4* q4 = reinterpret_cast<const float4*>(q);
                F4U r0, r1, r2, r3, r4, r5, r6, r7;
                r0.f = q4[0]; r1.f = q4[1]; r2.f = q4[2]; r3.f = q4[3];
                r4.f = q4[4]; r5.f = q4[5]; r6.f = q4[6]; r7.f = q4[7];
                u64 q16 = q[16];
                u64 k0 = splat2(wr[j * 3 + 0]);
                u64 k1 = splat2(wr[j * 3 + 1]);
                u64 k2 = splat2(wr[j * 3 + 2]);
                s[0] = fma2(k0, r0.u[0], s[0]); s[0] = fma2(k1, r0.u[1], s[0]); s[0] = fma2(k2, r1.u[0], s[0]);
                s[1] = fma2(k0, r1.u[0], s[1]); s[1] = fma2(k1, r1.u[1], s[1]); s[1] = fma2(k2, r2.u[0], s[1]);
                s[2] = fma2(k0, r2.u[0], s[2]); s[2] = fma2(k1, r2.u[1], s[2]); s[2] = fma2(k2, r3.u[0], s[2]);
                s[3] = fma2(k0, r3.u[0], s[3]); s[3] = fma2(k1, r3.u[1], s[3]); s[3] = fma2(k2, r4.u[0], s[3]);
                s[4] = fma2(k0, r4.u[0], s[4]); s[4] = fma2(k1, r4.u[1], s[4]); s[4] = fma2(k2, r5.u[0], s[4]);
                s[5] = fma2(k0, r5.u[0], s[5]); s[5] = fma2(k1, r5.u[1], s[5]); s[5] = fma2(k2, r6.u[0], s[5]);
                s[6] = fma2(k0, r6.u[0], s[6]); s[6] = fma2(k1, r6.u[1], s[6]); s[6] = fma2(k2, r7.u[0], s[6]);
                s[7] = fma2(k0, r7.u[0], s[7]); s[7] = fma2(k1, r7.u[1], s[7]); s[7] = fma2(k2, q16,     s[7]);
            }
#pragma unroll
            for (int p = 0; p < 8; p++) sm->red[cig][p][co] = s[p];
        } else {
            // ================= EDGE warps: fetch neighbor halo + matvec =====
            const int lane = tid & 31;
            if (tid < NBULK + 32) {
                // warp 16: LEFT side (tap 0, neighbor bid-1's w=15 column)
                if (t > 0) {
                    if (lane == 0)
                        while (ld_acq(&g_progress[bid - 1]) < need) { }
                    __syncwarp();
                    const float2* hp = reinterpret_cast<const float2*>(
                        &g_halo[par][bid - 1][1][0]);
                    float2 hv = __ldcg(hp + lane);
                    *reinterpret_cast<float2*>(&sm->hL[lane * 2]) = hv;
                    __syncwarp();
                    float c0 = 0.f, c1 = 0.f;
#pragma unroll 16
                    for (int ci = 0; ci < CH; ci++) {
                        float hvv = sm->hL[ci];
                        c0 = fmaf(sm->wE0[ci][lane],      hvv, c0);
                        c1 = fmaf(sm->wE0[ci][lane + 32], hvv, c1);
                    }
                    sm->corrL[lane]      = c0;
                    sm->corrL[lane + 32] = c1;
                }
            } else {
                // warp 17: RIGHT side (tap 2, neighbor bid+1's w=0 column)
                if (t < NT - 1) {
                    if (lane == 0)
                        while (ld_acq(&g_progress[bid + 1]) < need) { }
                    __syncwarp();
                    const float2* hp = reinterpret_cast<const float2*>(
                        &g_halo[par][bid + 1][0][0]);
                    float2 hv = __ldcg(hp + lane);
                    *reinterpret_cast<float2*>(&sm->hR[lane * 2]) = hv;
                    __syncwarp();
                    float c0 = 0.f, c1 = 0.f;
#pragma unroll 16
                    for (int ci = 0; ci < CH; ci++) {
                        float hvv = sm->hR[ci];
                        c0 = fmaf(sm->wE2[ci][lane],      hvv, c0);
                        c1 = fmaf(sm->wE2[ci][lane + 32], hvv, c1);
                    }
                    sm->corrR[lane]      = c0;
                    sm->corrR[lane + 32] = c1;
                }
            }
        }
        __syncthreads();   // S2: partials + corrections visible

        if (tid < NBULK) {
            // ================= BULK: reduce + activate + publish ============
            u64 acc = sm->red[0][cig][co];
#pragma unroll
            for (int c = 1; c < NCIG; c++) acc = add2(acc, sm->red[c][cig][co]);
            float slo, shi;
            unpack2(acc, slo, shi);
            if (cig == 0)        slo += sm->corrL[co];
            if (cig == NCIG - 1) shi += sm->corrR[co];
            float y0 = x2.x + ftanh(slo + bias);
            float y1 = x2.y + ftanh(shi + bias);

            *reinterpret_cast<float2*>(out + rb + o0) = make_float2(y0, y1);

            float2* pr = reinterpret_cast<float2*>(&sm->pp[cur ^ 1][co][0]);
            pr[o0].y = y0; pr[o0 + 1].x = y0;
            pr[o0 + 1].y = y1; pr[o0 + 2].x = y1;

            if (cig == 0)        g_halo[h & 1][bid][0][co] = y0;  // w = 0
            if (cig == NCIG - 1) g_halo[h & 1][bid][1][co] = y1;  // w = 15
        }
        __syncthreads();   // S3: pp + halo stores done
        if (tid == NBULK) st_rel(&g_progress[bid], h);
        cur ^= 1;
    }
}

extern "C" void kernel_launch(void* const* d_in, const int* in_sizes, int n_in,
                              void* d_out, int out_size) {
    const float* X  = (const float*)d_in[0];
    const float* Wc = (const float*)d_in[1];
    const float* bc = (const float*)d_in[2];
    float* out = (float*)d_out;

    cudaFuncSetAttribute(spatial_kernel,
                         cudaFuncAttributeMaxDynamicSharedMemorySize,
                         (int)sizeof(SMEMT));

    reset_kernel<<<1, NCTA>>>();
    spatial_kernel<<<NCTA, NTHR, sizeof(SMEMT)>>>(X, Wc, bc, out);
}

// round 14
// speedup vs baseline: 1.1761x; 1.1761x over previous
#include <cuda_runtime.h>

#define BATCH 8
#define CH    64
#define HH    256
#define WW    256
#define TW    16
#define NT    16                 // tiles along W
#define NCTA  (BATCH * NT)       // 128 CTAs, one wave
#define NTHR  1024               // 64 co x 8 cig x 2 w-halves
#define CIPT  8                  // ci per thread
#define NCIG  8
#define PSTR  18                 // pp row stride in u64 (144 B, 16B-aligned)

typedef unsigned long long u64;

union F4U { float4 f; u64 u[2]; };

__device__ int   g_progress[NCTA];
__device__ float g_halo[2][NCTA][2][CH];   // [row parity][cta][left/right edge][ch]

// ---- packed f32x2 ops ------------------------------------------------------
static __device__ __forceinline__ u64 fma2(u64 a, u64 b, u64 c) {
    u64 d; asm("fma.rn.f32x2 %0, %1, %2, %3;" : "=l"(d) : "l"(a), "l"(b), "l"(c)); return d;
}
static __device__ __forceinline__ u64 add2(u64 a, u64 b) {
    u64 d; asm("add.rn.f32x2 %0, %1, %2;" : "=l"(d) : "l"(a), "l"(b)); return d;
}
static __device__ __forceinline__ u64 splat2(float x) {
    u64 r; asm("mov.b64 %0, {%1, %1};" : "=l"(r) : "f"(x)); return r;
}
static __device__ __forceinline__ u64 pack2(float lo, float hi) {
    u64 r; asm("mov.b64 %0, {%1, %2};" : "=l"(r) : "f"(lo), "f"(hi)); return r;
}
static __device__ __forceinline__ void unpack2(u64 v, float& lo, float& hi) {
    unsigned a, b;
    asm("mov.b64 {%0,%1}, %2;" : "=r"(a), "=r"(b) : "l"(v));
    lo = __uint_as_float(a); hi = __uint_as_float(b);
}
static __device__ __forceinline__ float ftanh(float x) {
    float e = __expf(2.0f * x);
    return 1.0f - __fdividef(2.0f, e + 1.0f);
}

// ---- release/acquire flag ops ----------------------------------------------
static __device__ __forceinline__ int ld_acq(const int* p) {
    int v;
    asm volatile("ld.acquire.gpu.global.b32 %0, [%1];" : "=r"(v) : "l"(p));
    return v;
}
static __device__ __forceinline__ void st_rel(int* p, int v) {
    asm volatile("st.release.gpu.global.b32 [%0], %1;" :: "l"(p), "r"(v) : "memory");
}

__global__ void reset_kernel() {
    if (threadIdx.x < NCTA) g_progress[threadIdx.x] = -1;
}

__global__ void __launch_bounds__(NTHR, 1)
spatial_kernel(const float* __restrict__ X, const float* __restrict__ Wc,
               const float* __restrict__ bc, float* __restrict__ out) {
    __shared__ u64 pp[2][CH][PSTR];          // pair rows (v[j-1],v[j]), dbl buf 18 KB
    __shared__ u64 red[NCIG][NCIG][CH];      // partials [pair][cig][co]       32 KB

    const int tid = threadIdx.x;
    const int co  = tid & 63;            // channel
    const int cig = (tid >> 6) & 7;      // ci-group
    const int ws  = tid >> 9;            // 0: cols 0-7, 1: cols 8-15
    const int bid = blockIdx.x;
    const int b   = bid >> 4;
    const int t   = bid & 15;            // tile position along W
    const int w0  = t * TW;

    // finalizer identity (tid < 512): output pair pr_f of channel co
    const int pr_f = (tid >> 6) & 7;     // pair index 0..7 (cols 2p, 2p+1)
    const int o0   = pr_f * 2;

    // ---- weights: 8 ci x 3 taps into registers ----
    float wr[CIPT * 3];
    {
        const float4* wp = reinterpret_cast<const float4*>(
            Wc + ((size_t)co * CH + cig * CIPT) * 3);
#pragma unroll
        for (int i = 0; i < 6; i++) {
            float4 v = wp[i];
            wr[i * 4 + 0] = v.x; wr[i * 4 + 1] = v.y;
            wr[i * 4 + 2] = v.z; wr[i * 4 + 3] = v.w;
        }
    }
    const float bias = bc[co];

    // permanent zero halo slots: pp[j=0].lo and pp[j=16].hi never written elsewhere
    if (tid < CH) {
        reinterpret_cast<float2*>(&pp[0][tid][0])->x  = 0.f;
        reinterpret_cast<float2*>(&pp[1][tid][0])->x  = 0.f;
        reinterpret_cast<float2*>(&pp[0][tid][16])->y = 0.f;
        reinterpret_cast<float2*>(&pp[1][tid][16])->y = 0.f;
    }

    // ---- row 0: Y[0] = X[0] (finalizers only) ----
    const size_t chb = ((size_t)(b * CH + co) * HH) * WW + w0;
    if (tid < 512) {
        float2 x2 = *reinterpret_cast<const float2*>(X + chb + o0);
        *reinterpret_cast<float2*>(out + chb + o0) = x2;
        float2* pr = reinterpret_cast<float2*>(&pp[0][co][0]);
        pr[o0].y = x2.x; pr[o0 + 1].x = x2.x;
        pr[o0 + 1].y = x2.y; pr[o0 + 2].x = x2.y;
        if (pr_f == 0)        g_halo[0][bid][0][co] = x2.x;   // w = 0
        if (pr_f == NCIG - 1) g_halo[0][bid][1][co] = x2.y;   // w = 15
    }
    __syncthreads();
    if (tid == 0) st_rel(&g_progress[bid], 0);

    int cur = 0;
    for (int h = 1; h < HH; h++) {
        const int par  = (h - 1) & 1;
        const int need = h - 1;

        // ---- spin: exactly two pollster threads, pre-conv (R8 pattern) ----
        if (tid == 0 && t > 0)
            while (ld_acq(&g_progress[bid - 1]) < need) { }
        if (tid == 512 && t < NT - 1)
            while (ld_acq(&g_progress[bid + 1]) < need) { }
        __syncthreads();   // S1: neighbor row h-1 published

        // ---- issue long-latency loads; consumed after the conv ----
        // halo slice for this thread's 8 ci (warp-uniform address, 1 line)
        float4 m0 = make_float4(0.f,0.f,0.f,0.f), m1 = m0;
        if (ws == 0) {
            if (t > 0) {
                const float4* p4 = reinterpret_cast<const float4*>(
                    &g_halo[par][bid - 1][1][cig * CIPT]);
                m0 = __ldcg(p4); m1 = __ldcg(p4 + 1);
            }
        } else {
            if (t < NT - 1) {
                const float4* p4 = reinterpret_cast<const float4*>(
                    &g_halo[par][bid + 1][0][cig * CIPT]);
                m0 = __ldcg(p4); m1 = __ldcg(p4 + 1);
            }
        }
        const size_t rb = chb + (size_t)h * WW;
        float2 x2;
        if (tid < 512) x2 = *reinterpret_cast<const float2*>(X + rb + o0);

        // ---- conv: 8 ci rows x 8 cols (4 packed accumulators) ----
        u64 s0 = 0ull, s1 = 0ull, s2 = 0ull, s3 = 0ull;
        const u64* rowbase = &pp[cur][cig * CIPT][ws * 8];
#pragma unroll
        for (int j = 0; j < CIPT; j++) {
            const u64* q = rowbase + j * PSTR;
            const float4* q4 = reinterpret_cast<const float4*>(q);
            F4U r0, r1, r2, r3;
            r0.f = q4[0]; r1.f = q4[1]; r2.f = q4[2]; r3.f = q4[3];
            u64 q8 = q[8];
            u64 k0 = splat2(wr[j * 3 + 0]);
            u64 k1 = splat2(wr[j * 3 + 1]);
            u64 k2 = splat2(wr[j * 3 + 2]);
            s0 = fma2(k0, r0.u[0], s0); s0 = fma2(k1, r0.u[1], s0); s0 = fma2(k2, r1.u[0], s0);
            s1 = fma2(k0, r1.u[0], s1); s1 = fma2(k1, r1.u[1], s1); s1 = fma2(k2, r2.u[0], s1);
            s2 = fma2(k0, r2.u[0], s2); s2 = fma2(k1, r2.u[1], s2); s2 = fma2(k2, r3.u[0], s2);
            s3 = fma2(k0, r3.u[0], s3); s3 = fma2(k1, r3.u[1], s3); s3 = fma2(k2, q8,      s3);
        }

        // ---- halo correction over this thread's 8 ci (partial, pre-reduce) ----
        {
            float c = 0.f;
            if (ws == 0) {
                c = wr[0]  * m0.x + wr[3]  * m0.y + wr[6]  * m0.z + wr[9]  * m0.w
                  + wr[12] * m1.x + wr[15] * m1.y + wr[18] * m1.z + wr[21] * m1.w;
                float lo, hi; unpack2(s0, lo, hi); s0 = pack2(lo + c, hi);
            } else {
                c = wr[2]  * m0.x + wr[5]  * m0.y + wr[8]  * m0.z + wr[11] * m0.w
                  + wr[14] * m1.x + wr[17] * m1.y + wr[20] * m1.z + wr[23] * m1.w;
                float lo, hi; unpack2(s3, lo, hi); s3 = pack2(lo, hi + c);
            }
        }

        // ---- store partials: pair index P = ws*4 + a ----
        {
            const int pb = ws * 4;
            red[pb + 0][cig][co] = s0;
            red[pb + 1][cig][co] = s1;
            red[pb + 2][cig][co] = s2;
            red[pb + 3][cig][co] = s3;
        }
        __syncthreads();   // S2: partials visible

        // ---- finalizers: reduce 8 cigs, activate, publish ----
        if (tid < 512) {
            u64 acc = red[pr_f][0][co];
#pragma unroll
            for (int c = 1; c < NCIG; c++) acc = add2(acc, red[pr_f][c][co]);
            float slo, shi;
            unpack2(acc, slo, shi);
            float y0 = x2.x + ftanh(slo + bias);
            float y1 = x2.y + ftanh(shi + bias);

            *reinterpret_cast<float2*>(out + rb + o0) = make_float2(y0, y1);

            float2* pr = reinterpret_cast<float2*>(&pp[cur ^ 1][co][0]);
            pr[o0].y = y0; pr[o0 + 1].x = y0;
            pr[o0 + 1].y = y1; pr[o0 + 2].x = y1;

            if (pr_f == 0)        g_halo[h & 1][bid][0][co] = y0;  // w = 0
            if (pr_f == NCIG - 1) g_halo[h & 1][bid][1][co] = y1;  // w = 15
        }
        __syncthreads();   // S3: pp + halo stores done
        if (tid == 0) st_rel(&g_progress[bid], h);
        cur ^= 1;
    }
}

extern "C" void kernel_launch(void* const* d_in, const int* in_sizes, int n_in,
                              void* d_out, int out_size) {
    const float* X  = (const float*)d_in[0];
    const float* Wc = (const float*)d_in[1];
    const float* bc = (const float*)d_in[2];
    float* out = (float*)d_out;

    reset_kernel<<<1, NCTA>>>();
    spatial_kernel<<<NCTA, NTHR>>>(X, Wc, bc, out);
}

// round 15
// speedup vs baseline: 1.6900x; 1.4370x over previous
#include <cuda_runtime.h>

#define BATCH 8
#define CH    64
#define HH    256
#define WW    256
#define TW    16
#define NT    16                 // tiles along W
#define NCTA  (BATCH * NT)       // 128 CTAs, one wave
#define NTHR  512                // 64 co x 8 ci-groups
#define CIPT  8                  // ci per thread
#define NCIG  8
#define KROW  4                  // rows per halo exchange
#define NBLK  63                 // full blocks (rows 1..252); final block = 3 rows
#define WIDE  24                 // computed columns u = 0..23  (c = u - 4)
#define NP    12                 // output pairs per row
#define PSTR  26                 // pp row stride in u64 (25 used)

typedef unsigned long long u64;

union F4U { float4 f; u64 u[2]; };

__device__ int   g_progress[NCTA];
// [slot][cta][side 0=left-cols c0..3 / 1=right c12..15][colidx][co]
__device__ float g_halo[2][NCTA][2][KROW][CH];

struct SMEMT {
    u64 pp[2][CH][PSTR];         // duplicated-pair rows, dbl buf   26.6 KB
    u64 red[NP][NCIG][CH];       // partials                        48 KB
};

// ---- packed f32x2 ops ------------------------------------------------------
static __device__ __forceinline__ u64 fma2(u64 a, u64 b, u64 c) {
    u64 d; asm("fma.rn.f32x2 %0, %1, %2, %3;" : "=l"(d) : "l"(a), "l"(b), "l"(c)); return d;
}
static __device__ __forceinline__ u64 add2(u64 a, u64 b) {
    u64 d; asm("add.rn.f32x2 %0, %1, %2;" : "=l"(d) : "l"(a), "l"(b)); return d;
}
static __device__ __forceinline__ u64 splat2(float x) {
    u64 r; asm("mov.b64 %0, {%1, %1};" : "=l"(r) : "f"(x)); return r;
}
static __device__ __forceinline__ void unpack2(u64 v, float& lo, float& hi) {
    unsigned a, b;
    asm("mov.b64 {%0,%1}, %2;" : "=r"(a), "=r"(b) : "l"(v));
    lo = __uint_as_float(a); hi = __uint_as_float(b);
}
static __device__ __forceinline__ float ftanh(float x) {
    float e = __expf(2.0f * x);
    return 1.0f - __fdividef(2.0f, e + 1.0f);
}
static __device__ __forceinline__ int ld_acq(const int* p) {
    int v;
    asm volatile("ld.acquire.gpu.global.b32 %0, [%1];" : "=r"(v) : "l"(p));
    return v;
}
static __device__ __forceinline__ void st_rel(int* p, int v) {
    asm volatile("st.release.gpu.global.b32 [%0], %1;" :: "l"(p), "r"(v) : "memory");
}

__global__ void reset_kernel() {
    if (threadIdx.x < NCTA) g_progress[threadIdx.x] = -1;
}

__global__ void __launch_bounds__(NTHR, 1)
spatial_kernel(const float* __restrict__ X, const float* __restrict__ Wc,
               const float* __restrict__ bc, float* __restrict__ out) {
    extern __shared__ char smraw[];
    SMEMT* sm = reinterpret_cast<SMEMT*>(smraw);

    const int tid = threadIdx.x;
    const int co  = tid & 63;            // channel (conv + finalize)
    const int cig = tid >> 6;            // ci-group (conv)
    const int bid = blockIdx.x;
    const int b   = bid >> 4;
    const int t   = bid & 15;
    const int w0  = t * TW;

    // finalize identities: idx0 = tid -> pair P0; idx1 = 512+tid (tid<256) -> P1
    const int P0 = tid >> 6;             // 0..7
    const int P1 = 8 + (tid >> 6);       // 8..11 (valid for tid < 256)
    const int c0 = 2 * P0 - 4;           // cols of idx0: c0, c0+1   (-4..11)
    const int c1 = 2 * P1 - 4;           // cols of idx1: c1, c1+1   (12..19)
    const bool have1 = (tid < 256);
    const bool mask0 = (t == 0  && P0 < 2);    // c<0 at left edge
    const bool mask1 = (t == NT - 1 && P1 >= 10);  // c>15 at right edge
    const bool own0  = (P0 >= 2);        // idx0 owned cols iff P0 in [2,7]
    const bool own1  = (P1 <= 9);

    // ---- weights: 8 ci x 3 taps ----
    float wr[CIPT * 3];
    {
        const float4* wp = reinterpret_cast<const float4*>(
            Wc + ((size_t)co * CH + cig * CIPT) * 3);
#pragma unroll
        for (int i = 0; i < 6; i++) {
            float4 v = wp[i];
            wr[i * 4 + 0] = v.x; wr[i * 4 + 1] = v.y;
            wr[i * 4 + 2] = v.z; wr[i * 4 + 3] = v.w;
        }
    }
    const float bias = bc[co];

    if (tid < CH) {   // q[0].lo and q[24].hi stay 0 forever
        float* f0 = reinterpret_cast<float*>(&sm->pp[0][tid][0]);
        float* f1 = reinterpret_cast<float*>(&sm->pp[1][tid][0]);
        f0[0] = 0.f; f1[0] = 0.f; f0[49] = 0.f; f1[49] = 0.f;
    }
    __syncthreads();

    const size_t chbase = ((size_t)(b * CH + co) * HH) * WW + w0;

    // ---- row 0: Y[0] = X[0] over full 24-wide region ----
    {
        float2 x0 = make_float2(0.f, 0.f), x1 = x0;
        if (!mask0)          x0 = *reinterpret_cast<const float2*>(X + chbase + c0);
        if (have1 && !mask1) x1 = *reinterpret_cast<const float2*>(X + chbase + c1);
        float* fq = reinterpret_cast<float*>(&sm->pp[0][co][0]);
        fq[4*P0+1] = x0.x; fq[4*P0+2] = x0.x; fq[4*P0+3] = x0.y; fq[4*P0+4] = x0.y;
        if (own0) *reinterpret_cast<float2*>(out + chbase + c0) = x0;
        if (P0 == 2 || P0 == 3) {
            g_halo[0][bid][0][c0][co] = x0.x; g_halo[0][bid][0][c0+1][co] = x0.y;
        }
        if (have1) {
            fq[4*P1+1] = x1.x; fq[4*P1+2] = x1.x; fq[4*P1+3] = x1.y; fq[4*P1+4] = x1.y;
            if (own1) *reinterpret_cast<float2*>(out + chbase + c1) = x1;
            if (P1 == 8 || P1 == 9) {
                g_halo[0][bid][1][c1-12][co] = x1.x; g_halo[0][bid][1][c1-11][co] = x1.y;
            }
        }
    }
    __syncthreads();
    if (tid == 0) st_rel(&g_progress[bid], 0);

    int cur = 0;
    for (int blk = 0; blk <= NBLK; blk++) {
        const int slot = blk & 1;

        // ---- handshake: wait neighbors' base row (2 pollsters) ----
        if (tid == 0 && t > 0)
            while (ld_acq(&g_progress[bid - 1]) < blk) { }
        if (tid == 256 && t < NT - 1)
            while (ld_acq(&g_progress[bid + 1]) < blk) { }
        __syncthreads();   // S1

        // ---- patch base-row halo columns in pp[cur] ----
        if (tid < 64) {
            if (t > 0) {   // left: neighbor's c12..15 -> my u0..3
                float* fq = reinterpret_cast<float*>(&sm->pp[cur][tid][0]);
#pragma unroll
                for (int j = 0; j < KROW; j++) {
                    float v = g_halo[slot][bid - 1][1][j][tid];
                    fq[1 + 2*j] = v; fq[2 + 2*j] = v;
                }
            }
        } else if (tid < 128) {
            if (t < NT - 1) {   // right: neighbor's c0..3 -> my u20..23
                float* fq = reinterpret_cast<float*>(&sm->pp[cur][tid - 64][0]);
#pragma unroll
                for (int j = 0; j < KROW; j++) {
                    float v = g_halo[slot][bid + 1][0][j][tid - 64];
                    fq[41 + 2*j] = v; fq[42 + 2*j] = v;
                }
            }
        }
        __syncthreads();   // S1b: base row complete

        const int  jmax    = (blk == NBLK) ? 3 : KROW;
        const bool publish = (blk < NBLK);

        for (int j = 1; j <= jmax; j++) {
            const int r = blk * KROW + j;
            const size_t rbase = chbase + (size_t)r * WW;

            // X prefetch (consumed post-S2)
            float2 x0 = make_float2(0.f, 0.f), x1 = x0;
            if (!mask0)          x0 = *reinterpret_cast<const float2*>(X + rbase + c0);
            if (have1 && !mask1) x1 = *reinterpret_cast<const float2*>(X + rbase + c1);

            // ---- conv: 8 ci x 12 pairs ----
            u64 s[NP];
#pragma unroll
            for (int p = 0; p < NP; p++) s[p] = 0ull;
            const u64* rowb = &sm->pp[cur][cig * CIPT][0];
#pragma unroll
            for (int jc = 0; jc < CIPT; jc++) {
                const u64* q = rowb + jc * PSTR;
                const float4* q4 = reinterpret_cast<const float4*>(q);
                u64 k0 = splat2(wr[jc * 3 + 0]);
                u64 k1 = splat2(wr[jc * 3 + 1]);
                u64 k2 = splat2(wr[jc * 3 + 2]);
                {   // pairs 0..5 use q4[0..6]
                    F4U a0,a1,a2,a3,a4,a5,a6;
                    a0.f=q4[0]; a1.f=q4[1]; a2.f=q4[2]; a3.f=q4[3];
                    a4.f=q4[4]; a5.f=q4[5]; a6.f=q4[6];
                    s[0]=fma2(k0,a0.u[0],s[0]); s[0]=fma2(k1,a0.u[1],s[0]); s[0]=fma2(k2,a1.u[0],s[0]);
                    s[1]=fma2(k0,a1.u[0],s[1]); s[1]=fma2(k1,a1.u[1],s[1]); s[1]=fma2(k2,a2.u[0],s[1]);
                    s[2]=fma2(k0,a2.u[0],s[2]); s[2]=fma2(k1,a2.u[1],s[2]); s[2]=fma2(k2,a3.u[0],s[2]);
                    s[3]=fma2(k0,a3.u[0],s[3]); s[3]=fma2(k1,a3.u[1],s[3]); s[3]=fma2(k2,a4.u[0],s[3]);
                    s[4]=fma2(k0,a4.u[0],s[4]); s[4]=fma2(k1,a4.u[1],s[4]); s[4]=fma2(k2,a5.u[0],s[4]);
                    s[5]=fma2(k0,a5.u[0],s[5]); s[5]=fma2(k1,a5.u[1],s[5]); s[5]=fma2(k2,a6.u[0],s[5]);
                }
                {   // pairs 6..11 use q4[6..11] + q[24]
                    F4U a6,a7,a8,a9,a10,a11; u64 q24 = q[24];
                    a6.f=q4[6]; a7.f=q4[7]; a8.f=q4[8]; a9.f=q4[9];
                    a10.f=q4[10]; a11.f=q4[11];
                    s[6] =fma2(k0,a6.u[0], s[6]);  s[6] =fma2(k1,a6.u[1], s[6]);  s[6] =fma2(k2,a7.u[0], s[6]);
                    s[7] =fma2(k0,a7.u[0], s[7]);  s[7] =fma2(k1,a7.u[1], s[7]);  s[7] =fma2(k2,a8.u[0], s[7]);
                    s[8] =fma2(k0,a8.u[0], s[8]);  s[8] =fma2(k1,a8.u[1], s[8]);  s[8] =fma2(k2,a9.u[0], s[8]);
                    s[9] =fma2(k0,a9.u[0], s[9]);  s[9] =fma2(k1,a9.u[1], s[9]);  s[9] =fma2(k2,a10.u[0],s[9]);
                    s[10]=fma2(k0,a10.u[0],s[10]); s[10]=fma2(k1,a10.u[1],s[10]); s[10]=fma2(k2,a11.u[0],s[10]);
                    s[11]=fma2(k0,a11.u[0],s[11]); s[11]=fma2(k1,a11.u[1],s[11]); s[11]=fma2(k2,q24,     s[11]);
                }
            }
#pragma unroll
            for (int p = 0; p < NP; p++) sm->red[p][cig][co] = s[p];
            __syncthreads();   // S2

            // ---- finalize idx0 ----
            {
                u64 acc = sm->red[P0][0][co];
#pragma unroll
                for (int c = 1; c < NCIG; c++) acc = add2(acc, sm->red[P0][c][co]);
                float slo, shi; unpack2(acc, slo, shi);
                float y0 = x0.x + ftanh(slo + bias);
                float y1 = x0.y + ftanh(shi + bias);
                if (mask0) { y0 = 0.f; y1 = 0.f; }
                float* fq = reinterpret_cast<float*>(&sm->pp[cur ^ 1][co][0]);
                fq[4*P0+1] = y0; fq[4*P0+2] = y0; fq[4*P0+3] = y1; fq[4*P0+4] = y1;
                if (own0) *reinterpret_cast<float2*>(out + rbase + c0) = make_float2(y0, y1);
                if (publish && j == KROW && (P0 == 2 || P0 == 3)) {
                    g_halo[slot ^ 1][bid][0][c0][co]   = y0;
                    g_halo[slot ^ 1][bid][0][c0+1][co] = y1;
                }
            }
            // ---- finalize idx1 ----
            if (have1) {
                u64 acc = sm->red[P1][0][co];
#pragma unroll
                for (int c = 1; c < NCIG; c++) acc = add2(acc, sm->red[P1][c][co]);
                float slo, shi; unpack2(acc, slo, shi);
                float y0 = x1.x + ftanh(slo + bias);
                float y1 = x1.y + ftanh(shi + bias);
                if (mask1) { y0 = 0.f; y1 = 0.f; }
                float* fq = reinterpret_cast<float*>(&sm->pp[cur ^ 1][co][0]);
                fq[4*P1+1] = y0; fq[4*P1+2] = y0; fq[4*P1+3] = y1; fq[4*P1+4] = y1;
                if (own1) *reinterpret_cast<float2*>(out + rbase + c1) = make_float2(y0, y1);
                if (publish && j == KROW && (P1 == 8 || P1 == 9)) {
                    g_halo[slot ^ 1][bid][1][c1-12][co] = y0;
                    g_halo[slot ^ 1][bid][1][c1-11][co] = y1;
                }
            }
            __syncthreads();   // S3
            cur ^= 1;
        }

        if (tid == 0 && publish) st_rel(&g_progress[bid], blk + 1);
    }
}

extern "C" void kernel_launch(void* const* d_in, const int* in_sizes, int n_in,
                              void* d_out, int out_size) {
    const float* X  = (const float*)d_in[0];
    const float* Wc = (const float*)d_in[1];
    const float* bc = (const float*)d_in[2];
    float* out = (float*)d_out;

    cudaFuncSetAttribute(spatial_kernel,
                         cudaFuncAttributeMaxDynamicSharedMemorySize,
                         (int)sizeof(SMEMT));

    reset_kernel<<<1, NCTA>>>();
    spatial_kernel<<<NCTA, NTHR, sizeof(SMEMT)>>>(X, Wc, bc, out);
}